// round 14
// baseline (speedup 1.0000x reference)
#include <cuda_runtime.h>
#include <cuda_fp16.h>
#include <math.h>
#include <stdint.h>

// Problem constants (B=2, T=2048)
#define N_TOK 4096
#define CDIM  2048
#define EXPN  8
#define IDIM  5632

#define BMROWS 128
#define MAX_TILES 72
#define ROWS_PAD (MAX_TILES * BMROWS)    // 9216

#define BKH  64                          // K halves per chunk (128 B rows)
#define LDPH 72                          // padded stride (halves)
#define LDPB 144                         // padded stride (bytes)
#define STAGES 3
#define STG_B 36864                      // A 128*144 + B 128*144 bytes
#define B_OFF 18432u
#define B2_OFF 27648u
#define DSMEM_BYTES (STAGES * STG_B)     // 110592

#define NX8  ((N_TOK * CDIM) / 8)                        // 1048576
#define NW8  ((int)(((size_t)EXPN * IDIM * CDIM) / 8))   // 11534336
#define OUT4 ((N_TOK * CDIM) / 4)                        // 2097152

// ---------------- device scratch ----------------
__device__ int   g_row_token[ROWS_PAD];
__device__ float g_row_w[ROWS_PAD];
__device__ int   g_tile_expert[MAX_TILES];
__device__ int   g_cursor[EXPN];
__device__ int   g_off[EXPN];
__device__ int   g_tk_idx[N_TOK * 2];
__device__ float g_tk_w[N_TOK * 2];

__device__ __half g_xh[(size_t)N_TOK * CDIM];          // 16 MB
__device__ __half g_w1h[(size_t)EXPN * IDIM * CDIM];   // 176 MB
__device__ __half g_w2h[(size_t)EXPN * IDIM * CDIM];   // 176 MB
__device__ __half g_ph[(size_t)EXPN * CDIM * IDIM];    // 176 MB
__device__ __half g_h[(size_t)ROWS_PAD * IDIM];        // 104 MB

// ---------------- helpers ----------------
__device__ __forceinline__ uint32_t smem_u32(const void* p) {
    uint32_t a;
    asm("{ .reg .u64 t; cvta.to.shared.u64 t, %1; cvt.u32.u64 %0, t; }" : "=r"(a) : "l"(p));
    return a;
}
__device__ __forceinline__ void cp16(uint32_t dst, const void* src) {
    asm volatile("cp.async.cg.shared.global [%0], [%1], 16;" :: "r"(dst), "l"(src) : "memory");
}
__device__ __forceinline__ void cp_commit() { asm volatile("cp.async.commit_group;" ::: "memory"); }
__device__ __forceinline__ void cp_wait1() { asm volatile("cp.async.wait_group 1;" ::: "memory"); }
__device__ __forceinline__ void cp_wait0() { asm volatile("cp.async.wait_group 0;" ::: "memory"); }
__device__ __forceinline__ void red2(float* p, float v0, float v1) {
    asm volatile("red.global.add.v2.f32 [%0], {%1, %2};"
                 :: "l"(p), "f"(v0), "f"(v1) : "memory");
}
__device__ __forceinline__ uint4 cvt8(const float4* p) {
    float4 v0 = __ldg(p), v1 = __ldg(p + 1);
    __half2 a = __floats2half2_rn(v0.x, v0.y);
    __half2 b = __floats2half2_rn(v0.z, v0.w);
    __half2 c = __floats2half2_rn(v1.x, v1.y);
    __half2 d = __floats2half2_rn(v1.z, v1.w);
    uint4 o = { *(uint32_t*)&a, *(uint32_t*)&b, *(uint32_t*)&c, *(uint32_t*)&d };
    return o;
}

#define LDSM4(r0, r1, r2, r3, addr) \
    asm volatile("ldmatrix.sync.aligned.m8n8.x4.shared.b16 {%0,%1,%2,%3}, [%4];" \
        : "=r"(r0), "=r"(r1), "=r"(r2), "=r"(r3) : "r"(addr))

// NOT volatile: pure register op, lets ptxas schedule freely.
#define MMA_F16(d, a, b) asm( \
    "mma.sync.aligned.m16n8k16.row.col.f32.f16.f16.f32 " \
    "{%0,%1,%2,%3},{%4,%5,%6,%7},{%8,%9},{%0,%1,%2,%3};" \
    : "+f"((d)[0]), "+f"((d)[1]), "+f"((d)[2]), "+f"((d)[3]) \
    : "r"((a)[0]), "r"((a)[1]), "r"((a)[2]), "r"((a)[3]), \
      "r"((b)[0]), "r"((b)[1]))

// ========== K0: router (blocks [0,N_TOK)) fused with cvt of x/fc1/fc2 + reset ==========
__global__ void __launch_bounds__(256) prep_kernel(
        const float* __restrict__ x,   const float* __restrict__ gw,
        const float* __restrict__ fc1, const float* __restrict__ fc2) {
    if (blockIdx.x < N_TOK) {
        const int t = blockIdx.x;
        const float* xr = x + (size_t)t * CDIM;
        float acc[EXPN] = {};
        for (int k = threadIdx.x; k < CDIM; k += 256) {
            float xv = xr[k];
#pragma unroll
            for (int e = 0; e < EXPN; e++) acc[e] = fmaf(xv, gw[e * CDIM + k], acc[e]);
        }
#pragma unroll
        for (int off = 16; off > 0; off >>= 1)
#pragma unroll
            for (int e = 0; e < EXPN; e++)
                acc[e] += __shfl_down_sync(0xffffffffu, acc[e], off);

        __shared__ float sw[8][EXPN];
        __shared__ float slog[EXPN];
        int wid = threadIdx.x >> 5, lane = threadIdx.x & 31;
        if (lane == 0)
#pragma unroll
            for (int e = 0; e < EXPN; e++) sw[wid][e] = acc[e];
        __syncthreads();
        if (threadIdx.x < EXPN) {
            float s = 0.f;
#pragma unroll
            for (int w = 0; w < 8; w++) s += sw[w][threadIdx.x];
            slog[threadIdx.x] = s;
        }
        __syncthreads();
        if (threadIdx.x == 0) {
            int i0 = 0;
            for (int e = 1; e < EXPN; e++) if (slog[e] > slog[i0]) i0 = e;
            int i1 = (i0 == 0) ? 1 : 0;
            for (int e = 0; e < EXPN; e++)
                if (e != i0 && slog[e] > slog[i1]) i1 = e;
            float e1 = expf(slog[i1] - slog[i0]);
            float inv = 1.f / (1.f + e1);
            g_tk_idx[2 * t + 0] = i0;  g_tk_idx[2 * t + 1] = i1;
            g_tk_w[2 * t + 0] = inv;   g_tk_w[2 * t + 1] = e1 * inv;
        }
        return;
    }
    int ci = (blockIdx.x - N_TOK) * 256 + threadIdx.x;
    if (ci < ROWS_PAD) { g_row_token[ci] = 0; g_row_w[ci] = 0.f; }
    if (ci < MAX_TILES) g_tile_expert[ci] = -1;
    if (ci < EXPN) g_cursor[ci] = 0;

    const float* in;
    __half* out;
    int li;
    if (ci < NX8) { in = x; out = g_xh; li = ci; }
    else {
        int j = ci - NX8;
        if (j < NW8) { in = fc1; out = g_w1h; li = j; }
        else if (j < 2 * NW8) { in = fc2; out = g_w2h; li = j - NW8; }
        else return;
    }
    ((uint4*)out)[li] = cvt8((const float4*)in + 2 * (size_t)li);
}

// ========== sched: count + offsets + fill, one block ==========
__global__ void __launch_bounds__(1024) sched_kernel() {
    __shared__ int sc[EXPN];
    if (threadIdx.x < EXPN) sc[threadIdx.x] = 0;
    __syncthreads();
    for (int t = threadIdx.x; t < N_TOK; t += 1024) {
        atomicAdd(&sc[g_tk_idx[2 * t + 0]], 1);
        atomicAdd(&sc[g_tk_idx[2 * t + 1]], 1);
    }
    __syncthreads();
    if (threadIdx.x == 0) {
        int tileIdx = 0;
        for (int e = 0; e < EXPN; e++) {
            g_off[e] = tileIdx * BMROWS;
            int nt = (sc[e] + BMROWS - 1) / BMROWS;
            for (int j = 0; j < nt; j++) g_tile_expert[tileIdx++] = e;
        }
    }
    __syncthreads();
    for (int t = threadIdx.x; t < N_TOK; t += 1024) {
#pragma unroll
        for (int s = 0; s < 2; s++) {
            int e = g_tk_idx[2 * t + s];
            float w = g_tk_w[2 * t + s];
            int pos = atomicAdd(&g_cursor[e], 1);
            int r = g_off[e] + pos;
            g_row_token[r] = t;
            g_row_w[r] = w;
        }
    }
}

// =========== GEMM1 (fp16 mma) + service column ===========
__global__ void __launch_bounds__(256, 2) gemm1_kernel(
        const float* __restrict__ proj, float* __restrict__ out) {
    extern __shared__ char smc[];
    __shared__ int s_tok[BMROWS];
    __shared__ float s_w[BMROWS];

    if (blockIdx.y == 0) {
        const int nthr = MAX_TILES * 256;
        int base = blockIdx.x * 256 + threadIdx.x;
        float4 z = { 0.f, 0.f, 0.f, 0.f };
        for (int i = base; i < OUT4; i += nthr)
            ((float4*)out)[i] = z;
        for (int i = base; i < NW8; i += nthr)
            ((uint4*)g_ph)[i] = cvt8((const float4*)proj + 2 * (size_t)i);
        return;
    }

    const int tile = blockIdx.x;
    const int e = g_tile_expert[tile];
    if (e < 0) return;
    const int n0 = (blockIdx.y - 1) * 64;
    const int tid = threadIdx.x;
    const int wid = tid >> 5, lane = tid & 31;
    const int wm = wid >> 1, wn = wid & 1;
    const uint32_t dsm_u = smem_u32(smc);

    if (tid < BMROWS) {
        s_tok[tid] = g_row_token[tile * BMROWS + tid];
        s_w[tid]   = g_row_w[tile * BMROWS + tid];
    }
    __syncthreads();

    // compressed per-thread addresses (linear in j except A token gather)
    const int row0 = tid >> 3;
    const int c8 = (tid & 7) << 3;
    uint32_t aoff[4];
#pragma unroll
    for (int j = 0; j < 4; j++)
        aoff[j] = (uint32_t)s_tok[j * 32 + row0] * CDIM + c8;
    const uint32_t arel0 = (uint32_t)(row0 * LDPH + c8) * 2;
    const uint32_t soff0 = (uint32_t)e * (IDIM * CDIM) + (uint32_t)(n0 + row0) * CDIM + c8;

    const int lane16 = lane & 15;
    const uint32_t colsel = (uint32_t)((lane >> 4) << 4);
    uint32_t offA[2], offB1[2], offB2[2];
#pragma unroll
    for (int mt = 0; mt < 2; mt++)
        offA[mt] = (uint32_t)((wm * 32 + mt * 16 + lane16) * LDPB) + colsel;
#pragma unroll
    for (int p = 0; p < 2; p++) {
        offB1[p] = B_OFF + (uint32_t)((wn * 32 + p * 16 + lane16) * LDPB) + colsel;
        offB2[p] = offB1[p] + (B2_OFF - B_OFF);
    }

    float acc1[2][4][4] = {};
    float acc2[2][4][4] = {};
    const int NCH = CDIM / BKH;  // 32

    auto issue = [&](int c) {
        const uint32_t base = dsm_u + (uint32_t)(c % STAGES) * STG_B;
        const uint32_t k0 = (uint32_t)c * BKH;
#pragma unroll
        for (int j = 0; j < 4; j++)
            cp16(base + arel0 + j * (32 * LDPB), g_xh + aoff[j] + k0);
#pragma unroll
        for (int j = 0; j < 2; j++) {
            cp16(base + B_OFF + arel0 + j * (32 * LDPB), g_w1h + soff0 + j * (32 * CDIM) + k0);
            cp16(base + B2_OFF + arel0 + j * (32 * LDPB), g_w2h + soff0 + j * (32 * CDIM) + k0);
        }
        cp_commit();
    };

    issue(0);
    issue(1);

    for (int c = 0; c < NCH; c++) {
        if (c + 1 < NCH) cp_wait1(); else cp_wait0();
        __syncthreads();   // orders compute(c-1) before issue(c+2) overwrites
        if (c + 2 < NCH) issue(c + 2);

        const uint32_t sb = dsm_u + (uint32_t)(c % STAGES) * STG_B;
        uint32_t a[2][4], f1[2][4], f2[2][4];
        // preload B fragments for kk=0
#pragma unroll
        for (int p = 0; p < 2; p++) {
            LDSM4(f1[p][0], f1[p][1], f1[p][2], f1[p][3], sb + offB1[p]);
            LDSM4(f2[p][0], f2[p][1], f2[p][2], f2[p][3], sb + offB2[p]);
        }
#pragma unroll
        for (int kk = 0; kk < 4; kk++) {
            const uint32_t kb = (uint32_t)kk << 5;
            const uint32_t kbn = kb + 32;
#pragma unroll
            for (int mt = 0; mt < 2; mt++)
                LDSM4(a[mt][0], a[mt][1], a[mt][2], a[mt][3], sb + offA[mt] + kb);
#pragma unroll
            for (int p = 0; p < 2; p++) {
                uint32_t u0[2] = { f1[p][0], f1[p][2] }, u1[2] = { f1[p][1], f1[p][3] };
                uint32_t v0[2] = { f2[p][0], f2[p][2] }, v1[2] = { f2[p][1], f2[p][3] };
#pragma unroll
                for (int mt = 0; mt < 2; mt++) {
                    MMA_F16(acc1[mt][2 * p + 0], a[mt], u0);
                    MMA_F16(acc1[mt][2 * p + 1], a[mt], u1);
                    MMA_F16(acc2[mt][2 * p + 0], a[mt], v0);
                    MMA_F16(acc2[mt][2 * p + 1], a[mt], v1);
                }
                if (kk < 3) {   // rotate: reload B frags for kk+1 under remaining MMAs
                    LDSM4(f1[p][0], f1[p][1], f1[p][2], f1[p][3], sb + offB1[p] + kbn);
                    LDSM4(f2[p][0], f2[p][1], f2[p][2], f2[p][3], sb + offB2[p] + kbn);
                }
            }
        }
    }

    const int r4 = lane >> 2, cl = lane & 3;
#pragma unroll
    for (int mt = 0; mt < 2; mt++) {
#pragma unroll
        for (int hh = 0; hh < 2; hh++) {
            int lrow = wm * 32 + mt * 16 + r4 + 8 * hh;
            int grow = tile * BMROWS + lrow;
            float w = s_w[lrow];
            __half* hp = g_h + (size_t)grow * IDIM + n0 + wn * 32 + 2 * cl;
#pragma unroll
            for (int nt = 0; nt < 4; nt++) {
                float a0 = acc1[mt][nt][2 * hh + 0];
                float a1 = acc1[mt][nt][2 * hh + 1];
                float b0 = acc2[mt][nt][2 * hh + 0];
                float b1 = acc2[mt][nt][2 * hh + 1];
                float o0 = w * b0 * (a0 / (1.f + __expf(-a0)));
                float o1 = w * b1 * (a1 / (1.f + __expf(-a1)));
                *(__half2*)(hp + nt * 8) = __floats2half2_rn(o0, o1);
            }
        }
    }
}

// =========== GEMM2 (fp16 mma): out[token] += H @ proj^T ===========
__global__ void __launch_bounds__(256, 2) gemm2_kernel(float* __restrict__ out) {
    extern __shared__ char smc[];
    __shared__ int s_tok[BMROWS];

    const int tile = blockIdx.x;
    const int e = g_tile_expert[tile];
    if (e < 0) return;
    const int n0 = blockIdx.y * 128;
    const int tid = threadIdx.x;
    const int wid = tid >> 5, lane = tid & 31;
    const int wm = wid >> 1, wn = wid & 1;
    const uint32_t dsm_u = smem_u32(smc);

    if (tid < BMROWS) s_tok[tid] = g_row_token[tile * BMROWS + tid];
    __syncthreads();

    // compressed addresses (all linear in j)
    const int row0 = tid >> 3;
    const int c8 = (tid & 7) << 3;
    const uint32_t aoff0 = (uint32_t)(tile * BMROWS + row0) * IDIM + c8;
    const uint32_t boff0 = (uint32_t)e * (CDIM * IDIM) + (uint32_t)(n0 + row0) * IDIM + c8;
    const uint32_t arel0 = (uint32_t)(row0 * LDPH + c8) * 2;

    const int lane16 = lane & 15;
    const uint32_t colsel = (uint32_t)((lane >> 4) << 4);
    uint32_t offA[2], offB[4];
#pragma unroll
    for (int mt = 0; mt < 2; mt++)
        offA[mt] = (uint32_t)((wm * 32 + mt * 16 + lane16) * LDPB) + colsel;
#pragma unroll
    for (int p = 0; p < 4; p++)
        offB[p] = B_OFF + (uint32_t)((wn * 64 + p * 16 + lane16) * LDPB) + colsel;

    float acc[2][8][4] = {};
    const int NCH = IDIM / BKH;  // 88

    auto issue = [&](int c) {
        const uint32_t base = dsm_u + (uint32_t)(c % STAGES) * STG_B;
        const uint32_t k0 = (uint32_t)c * BKH;
#pragma unroll
        for (int j = 0; j < 4; j++) {
            cp16(base + arel0 + j * (32 * LDPB), g_h + aoff0 + j * (32 * IDIM) + k0);
            cp16(base + B_OFF + arel0 + j * (32 * LDPB), g_ph + boff0 + j * (32 * IDIM) + k0);
        }
        cp_commit();
    };

    issue(0);
    issue(1);

    for (int c = 0; c < NCH; c++) {
        if (c + 1 < NCH) cp_wait1(); else cp_wait0();
        __syncthreads();
        if (c + 2 < NCH) issue(c + 2);

        const uint32_t sb = dsm_u + (uint32_t)(c % STAGES) * STG_B;
        uint32_t a[2][2][4], fb[4][4];
        // preload kk=0 fragments
#pragma unroll
        for (int mt = 0; mt < 2; mt++)
            LDSM4(a[0][mt][0], a[0][mt][1], a[0][mt][2], a[0][mt][3], sb + offA[mt]);
#pragma unroll
        for (int p = 0; p < 4; p++)
            LDSM4(fb[p][0], fb[p][1], fb[p][2], fb[p][3], sb + offB[p]);
#pragma unroll
        for (int kk = 0; kk < 4; kk++) {
            const int cur = kk & 1, nxt = cur ^ 1;
            const uint32_t kbn = ((uint32_t)kk + 1) << 5;
            if (kk < 3) {   // prefetch next-kk A early (ping-pong)
#pragma unroll
                for (int mt = 0; mt < 2; mt++)
                    LDSM4(a[nxt][mt][0], a[nxt][mt][1], a[nxt][mt][2], a[nxt][mt][3],
                          sb + offA[mt] + kbn);
            }
#pragma unroll
            for (int p = 0; p < 4; p++) {
                uint32_t u0[2] = { fb[p][0], fb[p][2] }, u1[2] = { fb[p][1], fb[p][3] };
#pragma unroll
                for (int mt = 0; mt < 2; mt++) {
                    MMA_F16(acc[mt][2 * p + 0], a[cur][mt], u0);
                    MMA_F16(acc[mt][2 * p + 1], a[cur][mt], u1);
                }
                if (kk < 3)   // rotate: reload this B frag for kk+1
                    LDSM4(fb[p][0], fb[p][1], fb[p][2], fb[p][3], sb + offB[p] + kbn);
            }
        }
    }

    // epilogue: vector reductions (2 real adds/elem on zeroed base -> deterministic)
    const int r4 = lane >> 2, cl = lane & 3;
#pragma unroll
    for (int mt = 0; mt < 2; mt++) {
#pragma unroll
        for (int hh = 0; hh < 2; hh++) {
            int lrow = wm * 32 + mt * 16 + r4 + 8 * hh;
            int tok = s_tok[lrow];
            float* op = out + (size_t)tok * CDIM + n0 + wn * 64 + 2 * cl;
#pragma unroll
            for (int nt = 0; nt < 8; nt++)
                red2(op + nt * 8, acc[mt][nt][2 * hh + 0], acc[mt][nt][2 * hh + 1]);
        }
    }
}

// ---------------- launch ----------------
extern "C" void kernel_launch(void* const* d_in, const int* in_sizes, int n_in,
                              void* d_out, int out_size) {
    const float* x    = (const float*)d_in[0];
    const float* gate = (const float*)d_in[1];
    const float* fc1  = (const float*)d_in[2];
    const float* fc2  = (const float*)d_in[3];
    const float* proj = (const float*)d_in[4];
    float* out = (float*)d_out;

    cudaFuncSetAttribute(gemm1_kernel, cudaFuncAttributeMaxDynamicSharedMemorySize, DSMEM_BYTES);
    cudaFuncSetAttribute(gemm2_kernel, cudaFuncAttributeMaxDynamicSharedMemorySize, DSMEM_BYTES);

    const int ncvt = (NX8 + 2 * NW8 + 255) / 256;
    prep_kernel<<<N_TOK + ncvt, 256>>>(x, gate, fc1, fc2);                         // 0
    sched_kernel<<<1, 1024>>>();                                                   // 1
    gemm1_kernel<<<dim3(MAX_TILES, IDIM / 64 + 1), 256, DSMEM_BYTES>>>(proj, out); // 2
    gemm2_kernel<<<dim3(MAX_TILES, CDIM / 128), 256, DSMEM_BYTES>>>(out);          // 3 (profiled)
}

// round 15
// speedup vs baseline: 1.0127x; 1.0127x over previous
#include <cuda_runtime.h>
#include <cuda_fp16.h>
#include <math.h>
#include <stdint.h>

// Problem constants (B=2, T=2048)
#define N_TOK 4096
#define CDIM  2048
#define EXPN  8
#define IDIM  5632

#define BMROWS 128
#define MAX_TILES 72
#define ROWS_PAD (MAX_TILES * BMROWS)    // 9216

#define BKH  64
#define LDPH 72
#define LDPB 144
#define STAGES 3
#define STG_B 36864
#define B_OFF 18432u
#define B2_OFF 27648u
#define DSMEM_BYTES (STAGES * STG_B)     // 110592

#define NSLICE1 (IDIM / 64)              // 88
#define NSLICE2 (CDIM / 128)             // 16
#define NG1 (MAX_TILES * NSLICE1)        // 6336
#define NG2 (MAX_TILES * NSLICE2)        // 1152
#define GRID_FUSED (MAX_TILES + NG1 + NG2)  // 7560

#define NX8  ((N_TOK * CDIM) / 8)
#define NW8  ((int)(((size_t)EXPN * IDIM * CDIM) / 8))
#define OUT4 ((N_TOK * CDIM) / 4)

// ---------------- device scratch ----------------
__device__ int   g_row_token[ROWS_PAD];
__device__ float g_row_w[ROWS_PAD];
__device__ int   g_tile_expert[MAX_TILES];
__device__ int   g_cursor[EXPN];
__device__ int   g_off[EXPN];
__device__ int   g_tk_idx[N_TOK * 2];
__device__ float g_tk_w[N_TOK * 2];
__device__ int   g_tile_done[MAX_TILES];
__device__ int   g_svc_done;

__device__ __half g_xh[(size_t)N_TOK * CDIM];
__device__ __half g_w1h[(size_t)EXPN * IDIM * CDIM];
__device__ __half g_w2h[(size_t)EXPN * IDIM * CDIM];
__device__ __half g_ph[(size_t)EXPN * CDIM * IDIM];
__device__ __half g_h[(size_t)ROWS_PAD * IDIM];

// ---------------- helpers ----------------
__device__ __forceinline__ uint32_t smem_u32(const void* p) {
    uint32_t a;
    asm("{ .reg .u64 t; cvta.to.shared.u64 t, %1; cvt.u32.u64 %0, t; }" : "=r"(a) : "l"(p));
    return a;
}
__device__ __forceinline__ void cp16(uint32_t dst, const void* src) {
    asm volatile("cp.async.cg.shared.global [%0], [%1], 16;" :: "r"(dst), "l"(src) : "memory");
}
__device__ __forceinline__ void cp_commit() { asm volatile("cp.async.commit_group;" ::: "memory"); }
__device__ __forceinline__ void cp_wait1() { asm volatile("cp.async.wait_group 1;" ::: "memory"); }
__device__ __forceinline__ void cp_wait0() { asm volatile("cp.async.wait_group 0;" ::: "memory"); }
__device__ __forceinline__ void red2(float* p, float v0, float v1) {
    asm volatile("red.global.add.v2.f32 [%0], {%1, %2};"
                 :: "l"(p), "f"(v0), "f"(v1) : "memory");
}
__device__ __forceinline__ int ld_acq(const int* p) {
    int v;
    asm volatile("ld.acquire.gpu.global.u32 %0, [%1];" : "=r"(v) : "l"(p) : "memory");
    return v;
}
__device__ __forceinline__ uint4 cvt8(const float4* p) {
    float4 v0 = __ldg(p), v1 = __ldg(p + 1);
    __half2 a = __floats2half2_rn(v0.x, v0.y);
    __half2 b = __floats2half2_rn(v0.z, v0.w);
    __half2 c = __floats2half2_rn(v1.x, v1.y);
    __half2 d = __floats2half2_rn(v1.z, v1.w);
    uint4 o = { *(uint32_t*)&a, *(uint32_t*)&b, *(uint32_t*)&c, *(uint32_t*)&d };
    return o;
}

#define LDSM4(r0, r1, r2, r3, addr) \
    asm volatile("ldmatrix.sync.aligned.m8n8.x4.shared.b16 {%0,%1,%2,%3}, [%4];" \
        : "=r"(r0), "=r"(r1), "=r"(r2), "=r"(r3) : "r"(addr))

#define MMA_F16(d, a, b) asm( \
    "mma.sync.aligned.m16n8k16.row.col.f32.f16.f16.f32 " \
    "{%0,%1,%2,%3},{%4,%5,%6,%7},{%8,%9},{%0,%1,%2,%3};" \
    : "+f"((d)[0]), "+f"((d)[1]), "+f"((d)[2]), "+f"((d)[3]) \
    : "r"((a)[0]), "r"((a)[1]), "r"((a)[2]), "r"((a)[3]), \
      "r"((b)[0]), "r"((b)[1]))

// ========== K0: router + cvt(x,fc1,fc2) + reset ==========
__global__ void __launch_bounds__(256) prep_kernel(
        const float* __restrict__ x,   const float* __restrict__ gw,
        const float* __restrict__ fc1, const float* __restrict__ fc2) {
    if (blockIdx.x < N_TOK) {
        const int t = blockIdx.x;
        const float* xr = x + (size_t)t * CDIM;
        float acc[EXPN] = {};
        for (int k = threadIdx.x; k < CDIM; k += 256) {
            float xv = xr[k];
#pragma unroll
            for (int e = 0; e < EXPN; e++) acc[e] = fmaf(xv, gw[e * CDIM + k], acc[e]);
        }
#pragma unroll
        for (int off = 16; off > 0; off >>= 1)
#pragma unroll
            for (int e = 0; e < EXPN; e++)
                acc[e] += __shfl_down_sync(0xffffffffu, acc[e], off);

        __shared__ float sw[8][EXPN];
        __shared__ float slog[EXPN];
        int wid = threadIdx.x >> 5, lane = threadIdx.x & 31;
        if (lane == 0)
#pragma unroll
            for (int e = 0; e < EXPN; e++) sw[wid][e] = acc[e];
        __syncthreads();
        if (threadIdx.x < EXPN) {
            float s = 0.f;
#pragma unroll
            for (int w = 0; w < 8; w++) s += sw[w][threadIdx.x];
            slog[threadIdx.x] = s;
        }
        __syncthreads();
        if (threadIdx.x == 0) {
            int i0 = 0;
            for (int e = 1; e < EXPN; e++) if (slog[e] > slog[i0]) i0 = e;
            int i1 = (i0 == 0) ? 1 : 0;
            for (int e = 0; e < EXPN; e++)
                if (e != i0 && slog[e] > slog[i1]) i1 = e;
            float e1 = expf(slog[i1] - slog[i0]);
            float inv = 1.f / (1.f + e1);
            g_tk_idx[2 * t + 0] = i0;  g_tk_idx[2 * t + 1] = i1;
            g_tk_w[2 * t + 0] = inv;   g_tk_w[2 * t + 1] = e1 * inv;
        }
        return;
    }
    int ci = (blockIdx.x - N_TOK) * 256 + threadIdx.x;
    if (ci < ROWS_PAD) { g_row_token[ci] = 0; g_row_w[ci] = 0.f; }
    if (ci < MAX_TILES) { g_tile_expert[ci] = -1; g_tile_done[ci] = 0; }
    if (ci < EXPN) g_cursor[ci] = 0;
    if (ci == 0) g_svc_done = 0;

    const float* in;
    __half* out;
    int li;
    if (ci < NX8) { in = x; out = g_xh; li = ci; }
    else {
        int j = ci - NX8;
        if (j < NW8) { in = fc1; out = g_w1h; li = j; }
        else if (j < 2 * NW8) { in = fc2; out = g_w2h; li = j - NW8; }
        else return;
    }
    ((uint4*)out)[li] = cvt8((const float4*)in + 2 * (size_t)li);
}

// ========== sched ==========
__global__ void __launch_bounds__(1024) sched_kernel() {
    __shared__ int sc[EXPN];
    if (threadIdx.x < EXPN) sc[threadIdx.x] = 0;
    __syncthreads();
    for (int t = threadIdx.x; t < N_TOK; t += 1024) {
        atomicAdd(&sc[g_tk_idx[2 * t + 0]], 1);
        atomicAdd(&sc[g_tk_idx[2 * t + 1]], 1);
    }
    __syncthreads();
    if (threadIdx.x == 0) {
        int tileIdx = 0;
        for (int e = 0; e < EXPN; e++) {
            g_off[e] = tileIdx * BMROWS;
            int nt = (sc[e] + BMROWS - 1) / BMROWS;
            for (int j = 0; j < nt; j++) g_tile_expert[tileIdx++] = e;
        }
    }
    __syncthreads();
    for (int t = threadIdx.x; t < N_TOK; t += 1024) {
#pragma unroll
        for (int s = 0; s < 2; s++) {
            int e = g_tk_idx[2 * t + s];
            float w = g_tk_w[2 * t + s];
            int pos = atomicAdd(&g_cursor[e], 1);
            int r = g_off[e] + pos;
            g_row_token[r] = t;
            g_row_w[r] = w;
        }
    }
}

// ========== fused: service | gemm1 | gemm2 (per-tile dependency counters) ==========
__global__ void __launch_bounds__(256, 2) gemm_fused_kernel(
        const float* __restrict__ proj, float* __restrict__ out) {
    extern __shared__ char smc[];
    __shared__ int s_tok[BMROWS];
    __shared__ float s_w[BMROWS];

    const int bid = blockIdx.x;
    const int tid = threadIdx.x;
    const int wid = tid >> 5, lane = tid & 31;
    const int wm = wid >> 1, wn = wid & 1;
    const uint32_t dsm_u = smem_u32(smc);
    const int lane16 = lane & 15;
    const uint32_t colsel = (uint32_t)((lane >> 4) << 4);

    // ------------------ SERVICE: zero out + cvt proj ------------------
    if (bid < MAX_TILES) {
        const int nthr = MAX_TILES * 256;
        int base = bid * 256 + tid;
        float4 z = { 0.f, 0.f, 0.f, 0.f };
        for (int i = base; i < OUT4; i += nthr)
            ((float4*)out)[i] = z;
        for (int i = base; i < NW8; i += nthr)
            ((uint4*)g_ph)[i] = cvt8((const float4*)proj + 2 * (size_t)i);
        __threadfence();
        __syncthreads();
        if (tid == 0) atomicAdd(&g_svc_done, 1);
        return;
    }

    // ------------------ GEMM1 ------------------
    if (bid < MAX_TILES + NG1) {
        const int w = bid - MAX_TILES;
        const int tile = w % MAX_TILES;
        const int n0 = (w / MAX_TILES) * 64;
        const int e = g_tile_expert[tile];
        if (e < 0) {
            if (tid == 0) atomicAdd(&g_tile_done[tile], 1);   // deadlock-safe
            return;
        }

        if (tid < BMROWS) {
            s_tok[tid] = g_row_token[tile * BMROWS + tid];
            s_w[tid]   = g_row_w[tile * BMROWS + tid];
        }
        __syncthreads();

        const uint32_t wb = (uint32_t)e * (IDIM * CDIM);
        uint32_t aoff[4], soff[2];
        uint32_t arel[4], brel[2];
#pragma unroll
        for (int j = 0; j < 4; j++) {
            int idx = (j << 8) + tid;
            int row = idx >> 3;
            int c8 = (idx & 7) << 3;
            aoff[j] = (uint32_t)s_tok[row] * CDIM + c8;
            arel[j] = (uint32_t)(row * LDPH + c8) * 2;
        }
#pragma unroll
        for (int j = 0; j < 2; j++) {
            int idx = (j << 8) + tid;
            int row = idx >> 3;
            int c8 = (idx & 7) << 3;
            soff[j] = wb + (uint32_t)(n0 + row) * CDIM + c8;
            brel[j] = (uint32_t)(row * LDPH + c8) * 2;
        }

        uint32_t offA[2], offB1[2], offB2[2];
#pragma unroll
        for (int mt = 0; mt < 2; mt++)
            offA[mt] = (uint32_t)((wm * 32 + mt * 16 + lane16) * LDPB) + colsel;
#pragma unroll
        for (int p = 0; p < 2; p++) {
            offB1[p] = B_OFF + (uint32_t)((wn * 32 + p * 16 + lane16) * LDPB) + colsel;
            offB2[p] = offB1[p] + (B2_OFF - B_OFF);
        }

        float acc1[2][4][4] = {};
        float acc2[2][4][4] = {};
        const int NCH = CDIM / BKH;  // 32

        auto issue = [&](int c) {
            const uint32_t base = dsm_u + (uint32_t)(c % STAGES) * STG_B;
            const uint32_t k0 = (uint32_t)c * BKH;
#pragma unroll
            for (int j = 0; j < 4; j++) cp16(base + arel[j], g_xh + aoff[j] + k0);
#pragma unroll
            for (int j = 0; j < 2; j++) {
                cp16(base + B_OFF + brel[j], g_w1h + soff[j] + k0);
                cp16(base + B2_OFF + brel[j], g_w2h + soff[j] + k0);
            }
            cp_commit();
        };

        issue(0);
        issue(1);

        for (int c = 0; c < NCH; c++) {
            if (c + 1 < NCH) cp_wait1(); else cp_wait0();
            __syncthreads();
            if (c + 2 < NCH) issue(c + 2);

            const uint32_t sb = dsm_u + (uint32_t)(c % STAGES) * STG_B;
#pragma unroll
            for (int kk = 0; kk < 4; kk++) {
                const uint32_t kb = (uint32_t)kk << 5;
                uint32_t a[2][4], f1[2][4], f2[2][4];
#pragma unroll
                for (int mt = 0; mt < 2; mt++)
                    LDSM4(a[mt][0], a[mt][1], a[mt][2], a[mt][3], sb + offA[mt] + kb);
#pragma unroll
                for (int p = 0; p < 2; p++)
                    LDSM4(f1[p][0], f1[p][1], f1[p][2], f1[p][3], sb + offB1[p] + kb);
#pragma unroll
                for (int p = 0; p < 2; p++)
                    LDSM4(f2[p][0], f2[p][1], f2[p][2], f2[p][3], sb + offB2[p] + kb);
#pragma unroll
                for (int p = 0; p < 2; p++) {
                    uint32_t u0[2] = { f1[p][0], f1[p][2] }, u1[2] = { f1[p][1], f1[p][3] };
                    uint32_t v0[2] = { f2[p][0], f2[p][2] }, v1[2] = { f2[p][1], f2[p][3] };
#pragma unroll
                    for (int mt = 0; mt < 2; mt++) {
                        MMA_F16(acc1[mt][2 * p + 0], a[mt], u0);
                        MMA_F16(acc1[mt][2 * p + 1], a[mt], u1);
                        MMA_F16(acc2[mt][2 * p + 0], a[mt], v0);
                        MMA_F16(acc2[mt][2 * p + 1], a[mt], v1);
                    }
                }
            }
        }

        const int r4 = lane >> 2, cl = lane & 3;
#pragma unroll
        for (int mt = 0; mt < 2; mt++) {
#pragma unroll
            for (int hh = 0; hh < 2; hh++) {
                int lrow = wm * 32 + mt * 16 + r4 + 8 * hh;
                int grow = tile * BMROWS + lrow;
                float w2 = s_w[lrow];
                __half* hp = g_h + (size_t)grow * IDIM + n0 + wn * 32 + 2 * cl;
#pragma unroll
                for (int nt = 0; nt < 4; nt++) {
                    float a0 = acc1[mt][nt][2 * hh + 0];
                    float a1 = acc1[mt][nt][2 * hh + 1];
                    float b0 = acc2[mt][nt][2 * hh + 0];
                    float b1 = acc2[mt][nt][2 * hh + 1];
                    float o0 = w2 * b0 * (a0 / (1.f + __expf(-a0)));
                    float o1 = w2 * b1 * (a1 / (1.f + __expf(-a1)));
                    *(__half2*)(hp + nt * 8) = __floats2half2_rn(o0, o1);
                }
            }
        }
        __threadfence();
        __syncthreads();
        if (tid == 0) atomicAdd(&g_tile_done[tile], 1);
        return;
    }

    // ------------------ GEMM2 ------------------
    {
        const int w = bid - (MAX_TILES + NG1);
        const int tile = w % MAX_TILES;
        const int n0 = (w / MAX_TILES) * 128;
        const int e = g_tile_expert[tile];
        if (e < 0) return;

        if (tid < BMROWS) s_tok[tid] = g_row_token[tile * BMROWS + tid];

        // wait: this tile's 88 gemm1 slices done + all 72 service CTAs done
        if (tid == 0) {
            while (ld_acq(&g_tile_done[tile]) < NSLICE1 ||
                   ld_acq(&g_svc_done) < MAX_TILES)
                __nanosleep(1000);
        }
        __syncthreads();

        const uint32_t abase = (uint32_t)(tile * BMROWS) * IDIM;
        const uint32_t bbase = (uint32_t)e * (CDIM * IDIM) + (uint32_t)n0 * IDIM;
        uint32_t aoff[4], boff[4], arel[4];
#pragma unroll
        for (int j = 0; j < 4; j++) {
            int idx = (j << 8) + tid;
            int row = idx >> 3;
            int c8 = (idx & 7) << 3;
            aoff[j] = abase + (uint32_t)row * IDIM + c8;
            boff[j] = bbase + (uint32_t)row * IDIM + c8;
            arel[j] = (uint32_t)(row * LDPH + c8) * 2;
        }

        uint32_t offA[2], offB[4];
#pragma unroll
        for (int mt = 0; mt < 2; mt++)
            offA[mt] = (uint32_t)((wm * 32 + mt * 16 + lane16) * LDPB) + colsel;
#pragma unroll
        for (int p = 0; p < 4; p++)
            offB[p] = B_OFF + (uint32_t)((wn * 64 + p * 16 + lane16) * LDPB) + colsel;

        float acc[2][8][4] = {};
        const int NCH = IDIM / BKH;  // 88

        auto issue = [&](int c) {
            const uint32_t base = dsm_u + (uint32_t)(c % STAGES) * STG_B;
            const uint32_t k0 = (uint32_t)c * BKH;
#pragma unroll
            for (int j = 0; j < 4; j++) {
                cp16(base + arel[j], g_h + aoff[j] + k0);
                cp16(base + B_OFF + arel[j], g_ph + boff[j] + k0);
            }
            cp_commit();
        };

        issue(0);
        issue(1);

        for (int c = 0; c < NCH; c++) {
            if (c + 1 < NCH) cp_wait1(); else cp_wait0();
            __syncthreads();
            if (c + 2 < NCH) issue(c + 2);

            const uint32_t sb = dsm_u + (uint32_t)(c % STAGES) * STG_B;
#pragma unroll
            for (int kk = 0; kk < 4; kk++) {
                const uint32_t kb = (uint32_t)kk << 5;
                uint32_t a[2][4], fb[4][4];
#pragma unroll
                for (int mt = 0; mt < 2; mt++)
                    LDSM4(a[mt][0], a[mt][1], a[mt][2], a[mt][3], sb + offA[mt] + kb);
#pragma unroll
                for (int p = 0; p < 4; p++)
                    LDSM4(fb[p][0], fb[p][1], fb[p][2], fb[p][3], sb + offB[p] + kb);
#pragma unroll
                for (int p = 0; p < 4; p++) {
                    uint32_t u0[2] = { fb[p][0], fb[p][2] }, u1[2] = { fb[p][1], fb[p][3] };
#pragma unroll
                    for (int mt = 0; mt < 2; mt++) {
                        MMA_F16(acc[mt][2 * p + 0], a[mt], u0);
                        MMA_F16(acc[mt][2 * p + 1], a[mt], u1);
                    }
                }
            }
        }

        const int r4 = lane >> 2, cl = lane & 3;
#pragma unroll
        for (int mt = 0; mt < 2; mt++) {
#pragma unroll
            for (int hh = 0; hh < 2; hh++) {
                int lrow = wm * 32 + mt * 16 + r4 + 8 * hh;
                int tok = s_tok[lrow];
                float* op = out + (size_t)tok * CDIM + n0 + wn * 64 + 2 * cl;
#pragma unroll
                for (int nt = 0; nt < 8; nt++)
                    red2(op + nt * 8, acc[mt][nt][2 * hh + 0], acc[mt][nt][2 * hh + 1]);
            }
        }
    }
}

// ---------------- launch ----------------
extern "C" void kernel_launch(void* const* d_in, const int* in_sizes, int n_in,
                              void* d_out, int out_size) {
    const float* x    = (const float*)d_in[0];
    const float* gate = (const float*)d_in[1];
    const float* fc1  = (const float*)d_in[2];
    const float* fc2  = (const float*)d_in[3];
    const float* proj = (const float*)d_in[4];
    float* out = (float*)d_out;

    cudaFuncSetAttribute(gemm_fused_kernel, cudaFuncAttributeMaxDynamicSharedMemorySize, DSMEM_BYTES);

    const int ncvt = (NX8 + 2 * NW8 + 255) / 256;
    prep_kernel<<<N_TOK + ncvt, 256>>>(x, gate, fc1, fc2);                 // 0
    sched_kernel<<<1, 1024>>>();                                           // 1
    gemm_fused_kernel<<<GRID_FUSED, 256, DSMEM_BYTES>>>(proj, out);        // 2
}